// round 13
// baseline (speedup 1.0000x reference)
#include <cuda_runtime.h>
#include <cuda_bf16.h>
#include <math.h>
#include <stdint.h>

#define S_LEN 1024
#define D_MODEL 4096
#define FF_DIM 14336
#define KVDIM 1024
#define N_HEADS 32
#define N_KV_HEADS 8
#define HEAD_DIM 128

// ---------------- fp32 scratch ----------------
__device__ float g_h[S_LEN * D_MODEL];
__device__ float g_q[S_LEN * D_MODEL];
__device__ float g_k[S_LEN * KVDIM];
__device__ float g_v[S_LEN * KVDIM];
__device__ float g_attn[S_LEN * D_MODEL];
__device__ float g_res1[S_LEN * D_MODEL];
__device__ float g_f[S_LEN * D_MODEL];
__device__ float g_gate[S_LEN * FF_DIM];
__device__ float g_up[S_LEN * FF_DIM];
__device__ float g_t0[S_LEN * 16];
__device__ float g_t1[S_LEN * 16];
__device__ float g_t2[S_LEN * 16];

// ---------------- int8 quantized scratch (hi=q1, lo=q0) + per-row scales ----------------
__device__ int8_t q_h1[S_LEN * D_MODEL],   q_h0[S_LEN * D_MODEL];   __device__ float s_h[S_LEN];
__device__ int8_t q_at1[S_LEN * D_MODEL],  q_at0[S_LEN * D_MODEL];  __device__ float s_at[S_LEN];
__device__ int8_t q_f1[S_LEN * D_MODEL],   q_f0[S_LEN * D_MODEL];   __device__ float s_f[S_LEN];
__device__ int8_t q_g1[S_LEN * FF_DIM],    q_g0[S_LEN * FF_DIM];    __device__ float s_g[S_LEN];
__device__ int8_t q_wq1[D_MODEL * D_MODEL], q_wq0[D_MODEL * D_MODEL]; __device__ float s_wq[D_MODEL];
__device__ int8_t q_wk1[KVDIM * D_MODEL],   q_wk0[KVDIM * D_MODEL];   __device__ float s_wk[KVDIM];
__device__ int8_t q_wv1[KVDIM * D_MODEL],   q_wv0[KVDIM * D_MODEL];   __device__ float s_wv[KVDIM];
__device__ int8_t q_wo1[D_MODEL * D_MODEL], q_wo0[D_MODEL * D_MODEL]; __device__ float s_wo[D_MODEL];
__device__ int8_t q_w11[FF_DIM * D_MODEL],  q_w10[FF_DIM * D_MODEL];  __device__ float s_w1[FF_DIM];
__device__ int8_t q_w31[FF_DIM * D_MODEL],  q_w30[FF_DIM * D_MODEL];  __device__ float s_w3[FF_DIM];
__device__ int8_t q_w21[D_MODEL * FF_DIM],  q_w20[D_MODEL * FF_DIM];  __device__ float s_w2[D_MODEL];

// ================= shared helpers =================
__device__ __forceinline__ uint32_t smem_u32(const void* p) {
    return (uint32_t)__cvta_generic_to_shared(p);
}
__device__ __forceinline__ uint32_t pack2(__nv_bfloat16 a, __nv_bfloat16 b) {
    uint16_t ra = *(uint16_t*)&a, rb = *(uint16_t*)&b;
    return (uint32_t)ra | ((uint32_t)rb << 16);
}
__device__ __forceinline__ void ldsm4(uint32_t* r, uint32_t addr) {
    asm volatile("ldmatrix.sync.aligned.m8n8.x4.shared.b16 {%0,%1,%2,%3}, [%4];"
                 : "=r"(r[0]), "=r"(r[1]), "=r"(r[2]), "=r"(r[3]) : "r"(addr));
}
__device__ __forceinline__ void mma_bf16(float* c, const uint32_t* a, const uint32_t* b) {
    asm volatile("mma.sync.aligned.m16n8k16.row.col.f32.bf16.bf16.f32 "
                 "{%0,%1,%2,%3}, {%4,%5,%6,%7}, {%8,%9}, {%0,%1,%2,%3};"
                 : "+f"(c[0]), "+f"(c[1]), "+f"(c[2]), "+f"(c[3])
                 : "r"(a[0]), "r"(a[1]), "r"(a[2]), "r"(a[3]), "r"(b[0]), "r"(b[1]));
}
__device__ __forceinline__ void mma_s8(int* c, const uint32_t* a, const uint32_t* b) {
    asm volatile("mma.sync.aligned.m16n8k32.row.col.s32.s8.s8.s32 "
                 "{%0,%1,%2,%3}, {%4,%5,%6,%7}, {%8,%9}, {%0,%1,%2,%3};"
                 : "+r"(c[0]), "+r"(c[1]), "+r"(c[2]), "+r"(c[3])
                 : "r"(a[0]), "r"(a[1]), "r"(a[2]), "r"(a[3]), "r"(b[0]), "r"(b[1]));
}
__device__ __forceinline__ void cvt_store8(__nv_bfloat16* hi_p, __nv_bfloat16* lo_p, float4 v) {
    __nv_bfloat16 h0 = __float2bfloat16_rn(v.x);
    __nv_bfloat16 h1 = __float2bfloat16_rn(v.y);
    __nv_bfloat16 h2 = __float2bfloat16_rn(v.z);
    __nv_bfloat16 h3 = __float2bfloat16_rn(v.w);
    __nv_bfloat16 l0 = __float2bfloat16_rn(v.x - __bfloat162float(h0));
    __nv_bfloat16 l1 = __float2bfloat16_rn(v.y - __bfloat162float(h1));
    __nv_bfloat16 l2 = __float2bfloat16_rn(v.z - __bfloat162float(h2));
    __nv_bfloat16 l3 = __float2bfloat16_rn(v.w - __bfloat162float(h3));
    uint2 wh; wh.x = pack2(h0, h1); wh.y = pack2(h2, h3);
    uint2 wl; wl.x = pack2(l0, l1); wl.y = pack2(l2, l3);
    *(uint2*)hi_p = wh;
    *(uint2*)lo_p = wl;
}
__device__ __forceinline__ void split_pair(float a, float b, uint32_t* hi, uint32_t* lo) {
    __nv_bfloat16 ha = __float2bfloat16_rn(a), hb = __float2bfloat16_rn(b);
    __nv_bfloat16 la = __float2bfloat16_rn(a - __bfloat162float(ha));
    __nv_bfloat16 lb = __float2bfloat16_rn(b - __bfloat162float(hb));
    *hi = pack2(ha, hb);
    *lo = pack2(la, lb);
}
__device__ __forceinline__ void cp_async16(uint32_t dst, const void* src) {
    asm volatile("cp.async.cg.shared.global [%0], [%1], 16;" :: "r"(dst), "l"(src) : "memory");
}
#define CP_COMMIT() asm volatile("cp.async.commit_group;" ::: "memory")
#define CP_WAIT2()  asm volatile("cp.async.wait_group 2;" ::: "memory")

// ---------------- rmsnorm ----------------
__global__ void rmsnorm_kernel(const float* __restrict__ x, const float* __restrict__ w,
                               float* __restrict__ o, int D) {
    int row = blockIdx.x;
    const float* xr = x + (size_t)row * D;
    float* orow = o + (size_t)row * D;
    float ss = 0.f;
    for (int c = threadIdx.x; c < D; c += blockDim.x) {
        float v = xr[c];
        ss += v * v;
    }
    __shared__ float sred[32];
    for (int off = 16; off; off >>= 1) ss += __shfl_xor_sync(0xffffffffu, ss, off);
    if ((threadIdx.x & 31) == 0) sred[threadIdx.x >> 5] = ss;
    __syncthreads();
    if (threadIdx.x < 32) {
        float v = (threadIdx.x < (blockDim.x >> 5)) ? sred[threadIdx.x] : 0.f;
        for (int off = 16; off; off >>= 1) v += __shfl_xor_sync(0xffffffffu, v, off);
        if (threadIdx.x == 0) sred[0] = v;
    }
    __syncthreads();
    float inv = rsqrtf(sred[0] / (float)D + 1e-5f);
    for (int c = threadIdx.x; c < D; c += blockDim.x)
        orow[c] = xr[c] * inv * w[c];
}

// ---------------- per-row 14-bit quantization: x = s * (q1*64 + q0) ----------------
__global__ void quant_rows(const float* __restrict__ X, int8_t* __restrict__ Q1,
                           int8_t* __restrict__ Q0, float* __restrict__ S, int K) {
    extern __shared__ float xs[];
    int row = blockIdx.x;
    int tid = threadIdx.x;
    const float4* src = (const float4*)(X + (size_t)row * K);
    int K4 = K >> 2;
    float mx = 0.f;
    for (int i = tid; i < K4; i += 256) {
        float4 v = src[i];
        *(float4*)&xs[i * 4] = v;
        mx = fmaxf(mx, fmaxf(fmaxf(fabsf(v.x), fabsf(v.y)), fmaxf(fabsf(v.z), fabsf(v.w))));
    }
    __shared__ float red[32];
    for (int off = 16; off; off >>= 1) mx = fmaxf(mx, __shfl_xor_sync(0xffffffffu, mx, off));
    if ((tid & 31) == 0) red[tid >> 5] = mx;
    __syncthreads();
    if (tid < 32) {
        float v = (tid < 8) ? red[tid] : 0.f;
        for (int off = 16; off; off >>= 1) v = fmaxf(v, __shfl_xor_sync(0xffffffffu, v, off));
        if (tid == 0) red[0] = v;
    }
    __syncthreads();
    float m = red[0];
    float inv = (m > 0.f) ? 8128.f / m : 0.f;
    if (tid == 0) S[row] = (m > 0.f) ? m / 8128.f : 0.f;
    for (int i = tid; i < K4; i += 256) {
        float4 v = *(float4*)&xs[i * 4];
        const float* pv = (const float*)&v;
        uint32_t p1 = 0, p0 = 0;
#pragma unroll
        for (int j = 0; j < 4; j++) {
            int q = __float2int_rn(pv[j] * inv);
            int q1 = __float2int_rn((float)q * 0.015625f);
            int q0 = q - (q1 << 6);
            p1 |= ((uint32_t)(uint8_t)(int8_t)q1) << (8 * j);
            p0 |= ((uint32_t)(uint8_t)(int8_t)q0) << (8 * j);
        }
        *(uint32_t*)&Q1[(size_t)row * K + i * 4] = p1;
        *(uint32_t*)&Q0[(size_t)row * K + i * 4] = p0;
    }
}

// ---------------- LoRA down-projection: T[M,16] = X[M,K] @ A[16,K]^T (tiled) ----------------
__global__ void lora_a_kernel(const float* __restrict__ X, const float* __restrict__ A,
                              float* __restrict__ T, int K) {
    __shared__ float Xs[16][132];
    __shared__ float As[16][132];
    int m0 = blockIdx.x * 16;
    int tid = threadIdx.x;          // 256 threads
    int mi = tid >> 4, ni = tid & 15;
    float acc = 0.f;
    for (int k0 = 0; k0 < K; k0 += 128) {
#pragma unroll
        for (int i = 0; i < 2; i++) {
            int u = tid + i * 256;
            int r = u >> 5, c = (u & 31) * 4;
            *(float4*)&Xs[r][c] = *(const float4*)&X[(size_t)(m0 + r) * K + k0 + c];
            *(float4*)&As[r][c] = *(const float4*)&A[(size_t)r * K + k0 + c];
        }
        __syncthreads();
#pragma unroll
        for (int c = 0; c < 128; c += 4) {
            float4 x = *(float4*)&Xs[mi][c];
            float4 a = *(float4*)&As[ni][c];
            acc += x.x * a.x + x.y * a.y + x.z * a.z + x.w * a.w;
        }
        __syncthreads();
    }
    T[(m0 + mi) * 16 + ni] = acc;
}

// ================= int8 3-term IMMA GEMM =================
// C[M,N] = sA sB (4096*q1q1 + 64*(q1q0+q0q1)) + 2*T@LB^T (+resid)
// block 128x64, 8 warps (2m x 4n), warp tile 64x16, k-chunk 64 int8, 3-stage cp.async.
#define ISA1 0
#define ISA0 10240
#define ISB1 20480
#define ISB0 25600
#define ISTAGE 30720
#define IGEMM_SMEM (3 * ISTAGE + 128 * 16 * 4 + 64 * 16 * 4)   // 104448

__device__ __forceinline__ void ig_load_stage(uint32_t st, int tid,
    const int8_t* __restrict__ A1, const int8_t* __restrict__ A0,
    const int8_t* __restrict__ B1, const int8_t* __restrict__ B0,
    int m0, int n0, int K, int k0) {
#pragma unroll
    for (int i = 0; i < 6; i++) {
        int u = tid + i * 256;
        uint32_t dst; const int8_t* src;
        if (u < 512)       { int r = u >> 2,          sg = u & 3;
            dst = st + ISA1 + r * 80 + sg * 16; src = A1 + (size_t)(m0 + r) * K + k0 + sg * 16; }
        else if (u < 1024) { int v = u - 512;  int r = v >> 2, sg = v & 3;
            dst = st + ISA0 + r * 80 + sg * 16; src = A0 + (size_t)(m0 + r) * K + k0 + sg * 16; }
        else if (u < 1280) { int v = u - 1024; int r = v >> 2, sg = v & 3;
            dst = st + ISB1 + r * 80 + sg * 16; src = B1 + (size_t)(n0 + r) * K + k0 + sg * 16; }
        else               { int v = u - 1280; int r = v >> 2, sg = v & 3;
            dst = st + ISB0 + r * 80 + sg * 16; src = B0 + (size_t)(n0 + r) * K + k0 + sg * 16; }
        cp_async16(dst, src);
    }
}

__global__ void __launch_bounds__(256) igemm_lora(
    const int8_t* __restrict__ A1, const int8_t* __restrict__ A0, const float* __restrict__ sA,
    const int8_t* __restrict__ B1, const int8_t* __restrict__ B0, const float* __restrict__ sB,
    const float* __restrict__ T, const float* __restrict__ LB,
    const float* __restrict__ resid, float* __restrict__ C, int N, int K) {
    extern __shared__ char sm[];
    uint32_t sb = smem_u32(sm);
    float* Ts = (float*)(sm + 3 * ISTAGE);
    float* LBs = Ts + 128 * 16;

    int tid = threadIdx.x;
    int lane = tid & 31, warp = tid >> 5;
    int m0 = blockIdx.y * 128;
    int n0 = blockIdx.x * 64;

    for (int i = tid; i < 128 * 4; i += 256) {
        int r = i >> 2, c = (i & 3) * 4;
        *(float4*)&Ts[r * 16 + c] = *(const float4*)&T[(size_t)(m0 + r) * 16 + c];
    }
    for (int i = tid; i < 64 * 4; i += 256) {
        int r = i >> 2, c = (i & 3) * 4;
        *(float4*)&LBs[r * 16 + c] = *(const float4*)&LB[(size_t)(n0 + r) * 16 + c];
    }

    int wm = (warp >> 2) * 64;       // 0 or 64
    int wn = (warp & 3) * 16;        // 0..48
    int a_row = wm + (lane & 15);
    int a_k16 = (lane >> 4);         // 16B half within 32B k-step
    int b_row = wn + (lane & 7) + ((lane >> 4) << 3);
    int b_k16 = ((lane >> 3) & 1);

    int acc1[4][2][4], acc2[4][2][4];
#pragma unroll
    for (int mi = 0; mi < 4; mi++)
#pragma unroll
        for (int nt = 0; nt < 2; nt++)
#pragma unroll
            for (int e = 0; e < 4; e++) { acc1[mi][nt][e] = 0; acc2[mi][nt][e] = 0; }

    int NC = K >> 6;                 // >= 64 always here
    ig_load_stage(sb + 0 * ISTAGE, tid, A1, A0, B1, B0, m0, n0, K, 0);
    CP_COMMIT();
    ig_load_stage(sb + 1 * ISTAGE, tid, A1, A0, B1, B0, m0, n0, K, 64);
    CP_COMMIT();
    ig_load_stage(sb + 2 * ISTAGE, tid, A1, A0, B1, B0, m0, n0, K, 128);
    CP_COMMIT();

    int sidx = 0;
    for (int c = 0; c < NC; c++) {
        CP_WAIT2();
        __syncthreads();
        uint32_t st = sb + (uint32_t)sidx * ISTAGE;
#pragma unroll
        for (int ks = 0; ks < 2; ks++) {
            uint32_t a1f[4][4], a0f[4][4], b1f[4], b0f[4];
#pragma unroll
            for (int mi = 0; mi < 4; mi++) {
                uint32_t off = (uint32_t)(a_row + 16 * mi) * 80 + ks * 32 + a_k16 * 16;
                ldsm4(a1f[mi], st + ISA1 + off);
                ldsm4(a0f[mi], st + ISA0 + off);
            }
            uint32_t boff = (uint32_t)b_row * 80 + ks * 32 + b_k16 * 16;
            ldsm4(b1f, st + ISB1 + boff);
            ldsm4(b0f, st + ISB0 + boff);
#pragma unroll
            for (int mi = 0; mi < 4; mi++)
#pragma unroll
                for (int nt = 0; nt < 2; nt++) {
                    mma_s8(acc1[mi][nt], a1f[mi], &b1f[nt * 2]);
                    mma_s8(acc2[mi][nt], a1f[mi], &b0f[nt * 2]);
                    mma_s8(acc2[mi][nt], a0f[mi], &b1f[nt * 2]);
                }
        }
        __syncthreads();
        if (c + 3 < NC)
            ig_load_stage(sb + (uint32_t)sidx * ISTAGE, tid, A1, A0, B1, B0, m0, n0, K, (c + 3) * 64);
        CP_COMMIT();
        sidx = (sidx + 1) == 3 ? 0 : (sidx + 1);
    }

    // ---- epilogue: scale + LoRA rank16 + resid ----
    int rg = lane >> 2, cg = (lane & 3) * 2;
    float sbv[2][2];
#pragma unroll
    for (int nt = 0; nt < 2; nt++) {
        sbv[nt][0] = sB[n0 + wn + nt * 8 + cg];
        sbv[nt][1] = sB[n0 + wn + nt * 8 + cg + 1];
    }
#pragma unroll
    for (int mi = 0; mi < 4; mi++) {
#pragma unroll
        for (int p = 0; p < 2; p++) {
            int lr = wm + mi * 16 + rg + 8 * p;
            int row = m0 + lr;
            float sa = sA[row];
            size_t rb = (size_t)row * N;
#pragma unroll
            for (int nt = 0; nt < 2; nt++) {
                int lc = wn + nt * 8 + cg;
                int col = n0 + lc;
                float v0 = sa * sbv[nt][0] *
                           (4096.f * (float)acc1[mi][nt][p * 2] + 64.f * (float)acc2[mi][nt][p * 2]);
                float v1 = sa * sbv[nt][1] *
                           (4096.f * (float)acc1[mi][nt][p * 2 + 1] + 64.f * (float)acc2[mi][nt][p * 2 + 1]);
#pragma unroll
                for (int r = 0; r < 16; r++) {
                    float tv = 2.f * Ts[lr * 16 + r];
                    v0 += tv * LBs[lc * 16 + r];
                    v1 += tv * LBs[(lc + 1) * 16 + r];
                }
                if (resid != nullptr) {
                    float2 rr = *(const float2*)&resid[rb + col];
                    v0 += rr.x; v1 += rr.y;
                }
                *(float2*)&C[rb + col] = make_float2(v0, v1);
            }
        }
    }
}

// ---------------- RoPE ----------------
__global__ void rope_kernel(float* __restrict__ x, const float* __restrict__ cosb,
                            const float* __restrict__ sinb, int H) {
    int idx = blockIdx.x * blockDim.x + threadIdx.x;
    int total = S_LEN * H * 64;
    if (idx >= total) return;
    int i = idx & 63;
    int sh = idx >> 6;
    int s = sh / H;
    float c = cosb[s * 64 + i];
    float sn = sinb[s * 64 + i];
    float* p = x + (size_t)sh * 128 + 2 * i;
    float a = p[0], b = p[1];
    p[0] = a * c - b * sn;
    p[1] = a * sn + b * c;
}

// ================= tensor-core causal flash attention (bf16 3-term) =================
#define FQH 0
#define FQL 16384
#define FKH 32768
#define FKL 49152
#define FVH 65536
#define FVL 81920
#define FPH 98304
#define FPL 106496
#define FSTAT 114688
#define FLASH_TC_SMEM (114688 + 1024)

__global__ void __launch_bounds__(256) flash_tc(
    const float* __restrict__ Q, const float* __restrict__ K, const float* __restrict__ V,
    float* __restrict__ O) {
    extern __shared__ char smc[];
    uint32_t sb = smem_u32(smc);
    float* maxp = (float*)(smc + FSTAT);
    float* sump = maxp + 128;

    int h = blockIdx.x;
    int qb = (gridDim.y - 1) - blockIdx.y;
    int kvh = h >> 2;
    int tid = threadIdx.x;
    int lane = tid & 31, wid = tid >> 5;
    int warp_m = wid & 3, warp_n = wid >> 2;
    int q0 = qb * 64;

    int rg = lane >> 2;
    int cg = (lane & 3) * 2;
    int a_row16 = (lane & 15);
    int a_sel = lane >> 4;
    int b_roff = (lane & 7) + ((lane >> 4) << 3);
    int b_sel = (lane >> 3) & 1;

#pragma unroll
    for (int i = 0; i < 8; i++) {
        int u = tid + i * 256;
        int r = u >> 5;
        int col = (u & 31) * 4;
        float4 v = *(const float4*)&Q[(size_t)(q0 + r) * D_MODEL + h * HEAD_DIM + col];
        uint32_t adr = sb + FQH + r * 256 + ((((col >> 3) ^ (r & 7))) << 4) + (col & 7) * 2;
        __nv_bfloat16 tmp_h[4], tmp_l[4];
        cvt_store8(tmp_h, tmp_l, v);
        uint2 wh = *(uint2*)tmp_h, wl = *(uint2*)tmp_l;
        asm volatile("st.shared.v2.b32 [%0], {%1,%2};" :: "r"(adr), "r"(wh.x), "r"(wh.y) : "memory");
        asm volatile("st.shared.v2.b32 [%0], {%1,%2};" :: "r"(adr + (FQL - FQH)), "r"(wl.x), "r"(wl.y) : "memory");
    }

    float m_prev0 = -1e30f, m_prev1 = -1e30f, l0 = 0.f, l1 = 0.f;
    float oacc[8][4];
#pragma unroll
    for (int t = 0; t < 8; t++)
#pragma unroll
        for (int e = 0; e < 4; e++) oacc[t][e] = 0.f;

    int row_g0 = q0 + 16 * warp_m + rg;
    int row_g1 = row_g0 + 8;

    for (int kb = 0; kb <= qb; kb++) {
        int k0 = kb * 64;
        __syncthreads();
#pragma unroll
        for (int i = 0; i < 8; i++) {
            int u = tid + i * 256;
            int r = u >> 5;
            int col = (u & 31) * 4;
            float4 v = *(const float4*)&K[(size_t)(k0 + r) * KVDIM + kvh * HEAD_DIM + col];
            uint32_t adr = sb + FKH + r * 256 + ((((col >> 3) ^ (r & 7))) << 4) + (col & 7) * 2;
            __nv_bfloat16 th[4], tl[4];
            cvt_store8(th, tl, v);
            uint2 wh = *(uint2*)th, wl = *(uint2*)tl;
            asm volatile("st.shared.v2.b32 [%0], {%1,%2};" :: "r"(adr), "r"(wh.x), "r"(wh.y) : "memory");
            asm volatile("st.shared.v2.b32 [%0], {%1,%2};" :: "r"(adr + (FKL - FKH)), "r"(wl.x), "r"(wl.y) : "memory");
        }
#pragma unroll
        for (int i = 0; i < 4; i++) {
            int u = tid + i * 256;
            int kp = u & 31;
            int d = (u >> 5) * 4;
            float4 va = *(const float4*)&V[(size_t)(k0 + 2 * kp) * KVDIM + kvh * HEAD_DIM + d];
            float4 vb = *(const float4*)&V[(size_t)(k0 + 2 * kp + 1) * KVDIM + kvh * HEAD_DIM + d];
            const float* pa = (const float*)&va;
            const float* pb = (const float*)&vb;
            int colk = 2 * kp;
#pragma unroll
            for (int j = 0; j < 4; j++) {
                int dr = d + j;
                uint32_t hi, lo;
                split_pair(pa[j], pb[j], &hi, &lo);
                uint32_t adr = sb + FVH + dr * 128 + ((((colk >> 3) ^ (dr & 7))) << 4) + (colk & 7) * 2;
                asm volatile("st.shared.b32 [%0], %1;" :: "r"(adr), "r"(hi) : "memory");
                asm volatile("st.shared.b32 [%0], %1;" :: "r"(adr + (FVL - FVH)), "r"(lo) : "memory");
            }
        }
        __syncthreads();

        float sacc[4][4];
#pragma unroll
        for (int nt = 0; nt < 4; nt++)
#pragma unroll
            for (int e = 0; e < 4; e++) sacc[nt][e] = 0.f;
        int aq_row = 16 * warp_m + a_row16;
#pragma unroll
        for (int ks = 0; ks < 8; ks++) {
            uint32_t ahi[4], alo[4], khi[2][4], klo[2][4];
            uint32_t qa = sb + FQH + aq_row * 256 + ((((2 * ks + a_sel) ^ (aq_row & 7))) << 4);
            ldsm4(ahi, qa);
            ldsm4(alo, qa + (FQL - FQH));
#pragma unroll
            for (int j = 0; j < 2; j++) {
                int krow = 32 * warp_n + 16 * j + b_roff;
                uint32_t ka = sb + FKH + krow * 256 + ((((2 * ks + b_sel) ^ (krow & 7))) << 4);
                ldsm4(khi[j], ka);
                ldsm4(klo[j], ka + (FKL - FKH));
            }
#pragma unroll
            for (int nt = 0; nt < 4; nt++) {
                mma_bf16(sacc[nt], ahi, &khi[nt >> 1][(nt & 1) * 2]);
                mma_bf16(sacc[nt], ahi, &klo[nt >> 1][(nt & 1) * 2]);
                mma_bf16(sacc[nt], alo, &khi[nt >> 1][(nt & 1) * 2]);
            }
        }
        const float scale = 0.08838834764831845f;
#pragma unroll
        for (int nt = 0; nt < 4; nt++) {
            int cb = k0 + 32 * warp_n + 8 * nt + cg;
#pragma unroll
            for (int e = 0; e < 4; e++) sacc[nt][e] *= scale;
            if (kb == qb) {
                if (cb > row_g0) sacc[nt][0] = -1e30f;
                if (cb + 1 > row_g0) sacc[nt][1] = -1e30f;
                if (cb > row_g1) sacc[nt][2] = -1e30f;
                if (cb + 1 > row_g1) sacc[nt][3] = -1e30f;
            }
        }

        float mx0 = -1e30f, mx1 = -1e30f;
#pragma unroll
        for (int nt = 0; nt < 4; nt++) {
            mx0 = fmaxf(mx0, fmaxf(sacc[nt][0], sacc[nt][1]));
            mx1 = fmaxf(mx1, fmaxf(sacc[nt][2], sacc[nt][3]));
        }
        mx0 = fmaxf(mx0, __shfl_xor_sync(0xffffffffu, mx0, 1));
        mx0 = fmaxf(mx0, __shfl_xor_sync(0xffffffffu, mx0, 2));
        mx1 = fmaxf(mx1, __shfl_xor_sync(0xffffffffu, mx1, 1));
        mx1 = fmaxf(mx1, __shfl_xor_sync(0xffffffffu, mx1, 2));
        if ((lane & 3) == 0) {
            maxp[warp_n * 64 + 16 * warp_m + rg] = mx0;
            maxp[warp_n * 64 + 16 * warp_m + rg + 8] = mx1;
        }
        __syncthreads();
        int sidx0 = 16 * warp_m + rg, sidx1 = sidx0 + 8;
        float mb0 = fmaxf(maxp[sidx0], maxp[64 + sidx0]);
        float mb1 = fmaxf(maxp[sidx1], maxp[64 + sidx1]);
        float mn0 = fmaxf(m_prev0, mb0), mn1 = fmaxf(m_prev1, mb1);
        float corr0 = __expf(m_prev0 - mn0), corr1 = __expf(m_prev1 - mn1);

        float ps0 = 0.f, ps1 = 0.f;
#pragma unroll
        for (int nt = 0; nt < 4; nt++) {
            float p00 = __expf(sacc[nt][0] - mn0);
            float p01 = __expf(sacc[nt][1] - mn0);
            float p10 = __expf(sacc[nt][2] - mn1);
            float p11 = __expf(sacc[nt][3] - mn1);
            ps0 += p00 + p01;
            ps1 += p10 + p11;
            int col = 32 * warp_n + 8 * nt + cg;
            int r0 = 16 * warp_m + rg, r1 = r0 + 8;
            uint32_t hi, lo;
            split_pair(p00, p01, &hi, &lo);
            uint32_t a0 = sb + FPH + r0 * 128 + ((((col >> 3) ^ (r0 & 7))) << 4) + (col & 7) * 2;
            asm volatile("st.shared.b32 [%0], %1;" :: "r"(a0), "r"(hi) : "memory");
            asm volatile("st.shared.b32 [%0], %1;" :: "r"(a0 + (FPL - FPH)), "r"(lo) : "memory");
            split_pair(p10, p11, &hi, &lo);
            uint32_t a1 = sb + FPH + r1 * 128 + ((((col >> 3) ^ (r1 & 7))) << 4) + (col & 7) * 2;
            asm volatile("st.shared.b32 [%0], %1;" :: "r"(a1), "r"(hi) : "memory");
            asm volatile("st.shared.b32 [%0], %1;" :: "r"(a1 + (FPL - FPH)), "r"(lo) : "memory");
        }
        ps0 += __shfl_xor_sync(0xffffffffu, ps0, 1);
        ps0 += __shfl_xor_sync(0xffffffffu, ps0, 2);
        ps1 += __shfl_xor_sync(0xffffffffu, ps1, 1);
        ps1 += __shfl_xor_sync(0xffffffffu, ps1, 2);
        if ((lane & 3) == 0) {
            sump[warp_n * 64 + sidx0] = ps0;
            sump[warp_n * 64 + sidx1] = ps1;
        }
#pragma unroll
        for (int t = 0; t < 8; t++) {
            oacc[t][0] *= corr0; oacc[t][1] *= corr0;
            oacc[t][2] *= corr1; oacc[t][3] *= corr1;
        }
        l0 *= corr0; l1 *= corr1;
        m_prev0 = mn0; m_prev1 = mn1;
        __syncthreads();
        l0 += sump[sidx0] + sump[64 + sidx0];
        l1 += sump[sidx1] + sump[64 + sidx1];

#pragma unroll
        for (int kp = 0; kp < 4; kp++) {
            uint32_t phi[4], plo[4], vhi[4][4], vlo[4][4];
            int prow = 16 * warp_m + a_row16;
            uint32_t pa = sb + FPH + prow * 128 + ((((2 * kp + a_sel) ^ (prow & 7))) << 4);
            ldsm4(phi, pa);
            ldsm4(plo, pa + (FPL - FPH));
#pragma unroll
            for (int j = 0; j < 4; j++) {
                int vrow = 64 * warp_n + 16 * j + b_roff;
                uint32_t va = sb + FVH + vrow * 128 + ((((2 * kp + b_sel) ^ (vrow & 7))) << 4);
                ldsm4(vhi[j], va);
                ldsm4(vlo[j], va + (FVL - FVH));
            }
#pragma unroll
            for (int t = 0; t < 8; t++) {
                mma_bf16(oacc[t], phi, &vhi[t >> 1][(t & 1) * 2]);
                mma_bf16(oacc[t], phi, &vlo[t >> 1][(t & 1) * 2]);
                mma_bf16(oacc[t], plo, &vhi[t >> 1][(t & 1) * 2]);
            }
        }
    }

    float inv0 = 1.f / l0, inv1 = 1.f / l1;
#pragma unroll
    for (int t = 0; t < 8; t++) {
        int col = h * HEAD_DIM + 64 * warp_n + 8 * t + cg;
        float2 o0 = make_float2(oacc[t][0] * inv0, oacc[t][1] * inv0);
        float2 o1 = make_float2(oacc[t][2] * inv1, oacc[t][3] * inv1);
        *(float2*)&O[(size_t)row_g0 * D_MODEL + col] = o0;
        *(float2*)&O[(size_t)row_g1 * D_MODEL + col] = o1;
    }
}

// ---------------- silu(gate) * up ----------------
__global__ void silu_mul_kernel(const float* __restrict__ g, const float* __restrict__ u,
                                float* __restrict__ o, int n) {
    int i = blockIdx.x * blockDim.x + threadIdx.x;
    if (i < n) {
        float x = g[i];
        float s = x / (1.f + __expf(-x));
        o[i] = s * u[i];
    }
}

// ---------------- launch ----------------
extern "C" void kernel_launch(void* const* d_in, const int* in_sizes, int n_in,
                              void* d_out, int out_size) {
    const float* data = (const float*)d_in[0];
    const float* cosb = (const float*)d_in[2];
    const float* sinb = (const float*)d_in[3];
    const float* attn_norm_w = (const float*)d_in[4];
    const float* wq = (const float*)d_in[5];
    const float* wk = (const float*)d_in[6];
    const float* wv = (const float*)d_in[7];
    const float* wo = (const float*)d_in[8];
    const float* wq_a = (const float*)d_in[9];
    const float* wq_b = (const float*)d_in[10];
    const float* wk_a = (const float*)d_in[11];
    const float* wk_b = (const float*)d_in[12];
    const float* wv_a = (const float*)d_in[13];
    const float* wv_b = (const float*)d_in[14];
    const float* wo_a = (const float*)d_in[15];
    const float* wo_b = (const float*)d_in[16];
    const float* ffn_norm_w = (const float*)d_in[17];
    const float* w1 = (const float*)d_in[18];
    const float* w2 = (const float*)d_in[19];
    const float* w3 = (const float*)d_in[20];
    const float* w1_a = (const float*)d_in[21];
    const float* w1_b = (const float*)d_in[22];
    const float* w2_a = (const float*)d_in[23];
    const float* w2_b = (const float*)d_in[24];
    const float* w3_a = (const float*)d_in[25];
    const float* w3_b = (const float*)d_in[26];
    float* out = (float*)d_out;

    float *h, *q, *k, *v, *attn, *res1, *f, *gate, *up, *t0, *t1, *t2;
    cudaGetSymbolAddress((void**)&h, g_h);
    cudaGetSymbolAddress((void**)&q, g_q);
    cudaGetSymbolAddress((void**)&k, g_k);
    cudaGetSymbolAddress((void**)&v, g_v);
    cudaGetSymbolAddress((void**)&attn, g_attn);
    cudaGetSymbolAddress((void**)&res1, g_res1);
    cudaGetSymbolAddress((void**)&f, g_f);
    cudaGetSymbolAddress((void**)&gate, g_gate);
    cudaGetSymbolAddress((void**)&up, g_up);
    cudaGetSymbolAddress((void**)&t0, g_t0);
    cudaGetSymbolAddress((void**)&t1, g_t1);
    cudaGetSymbolAddress((void**)&t2, g_t2);

    int8_t *ph1, *ph0, *pat1, *pat0, *pf1, *pf0, *pg1, *pg0;
    int8_t *pwq1, *pwq0, *pwk1, *pwk0, *pwv1, *pwv0, *pwo1, *pwo0;
    int8_t *pw11, *pw10, *pw31, *pw30, *pw21, *pw20;
    float *psh, *psat, *psf, *psg, *pswq, *pswk, *pswv, *pswo, *psw1, *psw3, *psw2;
    cudaGetSymbolAddress((void**)&ph1, q_h1);   cudaGetSymbolAddress((void**)&ph0, q_h0);
    cudaGetSymbolAddress((void**)&pat1, q_at1); cudaGetSymbolAddress((void**)&pat0, q_at0);
    cudaGetSymbolAddress((void**)&pf1, q_f1);   cudaGetSymbolAddress((void**)&pf0, q_f0);
    cudaGetSymbolAddress((void**)&pg1, q_g1);   cudaGetSymbolAddress((void**)&pg0, q_g0);
    cudaGetSymbolAddress((void**)&pwq1, q_wq1); cudaGetSymbolAddress((void**)&pwq0, q_wq0);
    cudaGetSymbolAddress((void**)&pwk1, q_wk1); cudaGetSymbolAddress((void**)&pwk0, q_wk0);
    cudaGetSymbolAddress((void**)&pwv1, q_wv1); cudaGetSymbolAddress((void**)&pwv0, q_wv0);
    cudaGetSymbolAddress((void**)&pwo1, q_wo1); cudaGetSymbolAddress((void**)&pwo0, q_wo0);
    cudaGetSymbolAddress((void**)&pw11, q_w11); cudaGetSymbolAddress((void**)&pw10, q_w10);
    cudaGetSymbolAddress((void**)&pw31, q_w31); cudaGetSymbolAddress((void**)&pw30, q_w30);
    cudaGetSymbolAddress((void**)&pw21, q_w21); cudaGetSymbolAddress((void**)&pw20, q_w20);
    cudaGetSymbolAddress((void**)&psh, s_h);    cudaGetSymbolAddress((void**)&psat, s_at);
    cudaGetSymbolAddress((void**)&psf, s_f);    cudaGetSymbolAddress((void**)&psg, s_g);
    cudaGetSymbolAddress((void**)&pswq, s_wq);  cudaGetSymbolAddress((void**)&pswk, s_wk);
    cudaGetSymbolAddress((void**)&pswv, s_wv);  cudaGetSymbolAddress((void**)&pswo, s_wo);
    cudaGetSymbolAddress((void**)&psw1, s_w1);  cudaGetSymbolAddress((void**)&psw3, s_w3);
    cudaGetSymbolAddress((void**)&psw2, s_w2);

    cudaFuncSetAttribute(flash_tc, cudaFuncAttributeMaxDynamicSharedMemorySize, FLASH_TC_SMEM);
    cudaFuncSetAttribute(igemm_lora, cudaFuncAttributeMaxDynamicSharedMemorySize, IGEMM_SMEM);
    cudaFuncSetAttribute(quant_rows, cudaFuncAttributeMaxDynamicSharedMemorySize, FF_DIM * 4);

    // 0) quantize weights (per launch; deterministic)
    quant_rows<<<D_MODEL, 256, D_MODEL * 4>>>(wq, pwq1, pwq0, pswq, D_MODEL);
    quant_rows<<<KVDIM, 256, D_MODEL * 4>>>(wk, pwk1, pwk0, pswk, D_MODEL);
    quant_rows<<<KVDIM, 256, D_MODEL * 4>>>(wv, pwv1, pwv0, pswv, D_MODEL);
    quant_rows<<<D_MODEL, 256, D_MODEL * 4>>>(wo, pwo1, pwo0, pswo, D_MODEL);
    quant_rows<<<FF_DIM, 256, D_MODEL * 4>>>(w1, pw11, pw10, psw1, D_MODEL);
    quant_rows<<<FF_DIM, 256, D_MODEL * 4>>>(w3, pw31, pw30, psw3, D_MODEL);
    quant_rows<<<D_MODEL, 256, FF_DIM * 4>>>(w2, pw21, pw20, psw2, FF_DIM);

    // 1) attn rmsnorm + quantize h
    rmsnorm_kernel<<<S_LEN, 256>>>(data, attn_norm_w, h, D_MODEL);
    quant_rows<<<S_LEN, 256, D_MODEL * 4>>>(h, ph1, ph0, psh, D_MODEL);

    // 2) q/k/v projections with fused LoRA
    lora_a_kernel<<<S_LEN / 16, 256>>>(h, wq_a, t0, D_MODEL);
    lora_a_kernel<<<S_LEN / 16, 256>>>(h, wk_a, t1, D_MODEL);
    lora_a_kernel<<<S_LEN / 16, 256>>>(h, wv_a, t2, D_MODEL);
    igemm_lora<<<dim3(D_MODEL / 64, S_LEN / 128), 256, IGEMM_SMEM>>>(
        ph1, ph0, psh, pwq1, pwq0, pswq, t0, wq_b, nullptr, q, D_MODEL, D_MODEL);
    igemm_lora<<<dim3(KVDIM / 64, S_LEN / 128), 256, IGEMM_SMEM>>>(
        ph1, ph0, psh, pwk1, pwk0, pswk, t1, wk_b, nullptr, k, KVDIM, D_MODEL);
    igemm_lora<<<dim3(KVDIM / 64, S_LEN / 128), 256, IGEMM_SMEM>>>(
        ph1, ph0, psh, pwv1, pwv0, pswv, t2, wv_b, nullptr, v, KVDIM, D_MODEL);

    // 3) RoPE
    rope_kernel<<<(S_LEN * N_HEADS * 64) / 256, 256>>>(q, cosb, sinb, N_HEADS);
    rope_kernel<<<(S_LEN * N_KV_HEADS * 64) / 256, 256>>>(k, cosb, sinb, N_KV_HEADS);

    // 4) attention (tensor-core flash)
    flash_tc<<<dim3(N_HEADS, S_LEN / 64), 256, FLASH_TC_SMEM>>>(q, k, v, attn);

    // 5) output projection + residual
    quant_rows<<<S_LEN, 256, D_MODEL * 4>>>(attn, pat1, pat0, psat, D_MODEL);
    lora_a_kernel<<<S_LEN / 16, 256>>>(attn, wo_a, t0, D_MODEL);
    igemm_lora<<<dim3(D_MODEL / 64, S_LEN / 128), 256, IGEMM_SMEM>>>(
        pat1, pat0, psat, pwo1, pwo0, pswo, t0, wo_b, data, res1, D_MODEL, D_MODEL);

    // 6) ffn rmsnorm + quantize f
    rmsnorm_kernel<<<S_LEN, 256>>>(res1, ffn_norm_w, f, D_MODEL);
    quant_rows<<<S_LEN, 256, D_MODEL * 4>>>(f, pf1, pf0, psf, D_MODEL);

    // 7) gate / up
    lora_a_kernel<<<S_LEN / 16, 256>>>(f, w1_a, t0, D_MODEL);
    lora_a_kernel<<<S_LEN / 16, 256>>>(f, w3_a, t1, D_MODEL);
    igemm_lora<<<dim3(FF_DIM / 64, S_LEN / 128), 256, IGEMM_SMEM>>>(
        pf1, pf0, psf, pw11, pw10, psw1, t0, w1_b, nullptr, gate, FF_DIM, D_MODEL);
    igemm_lora<<<dim3(FF_DIM / 64, S_LEN / 128), 256, IGEMM_SMEM>>>(
        pf1, pf0, psf, pw31, pw30, psw3, t1, w3_b, nullptr, up, FF_DIM, D_MODEL);

    // 8) silu * up + quantize gate
    silu_mul_kernel<<<(S_LEN * FF_DIM) / 256, 256>>>(gate, up, gate, S_LEN * FF_DIM);
    quant_rows<<<S_LEN, 256, FF_DIM * 4>>>(gate, pg1, pg0, psg, FF_DIM);

    // 9) down projection + residual -> out
    lora_a_kernel<<<S_LEN / 16, 256>>>(gate, w2_a, t0, FF_DIM);
    igemm_lora<<<dim3(D_MODEL / 64, S_LEN / 128), 256, IGEMM_SMEM>>>(
        pg1, pg0, psg, pw21, pw20, psw2, t0, w2_b, res1, out, D_MODEL, FF_DIM);
}

// round 14
// speedup vs baseline: 2.3248x; 2.3248x over previous
#include <cuda_runtime.h>
#include <cuda_bf16.h>
#include <cuda_fp16.h>
#include <math.h>
#include <stdint.h>

#define S_LEN 1024
#define D_MODEL 4096
#define FF_DIM 14336
#define KVDIM 1024
#define N_HEADS 32
#define N_KV_HEADS 8
#define HEAD_DIM 128

// ---------------- scratch (static device globals; no allocation) ----------------
__device__ float g_h[S_LEN * D_MODEL];
__device__ float g_q[S_LEN * D_MODEL];
__device__ float g_k[S_LEN * KVDIM];
__device__ float g_v[S_LEN * KVDIM];
__device__ float g_attn[S_LEN * D_MODEL];
__device__ float g_res1[S_LEN * D_MODEL];
__device__ float g_f[S_LEN * D_MODEL];
__device__ float g_gate[S_LEN * FF_DIM];
__device__ float g_up[S_LEN * FF_DIM];
__device__ float g_t0[S_LEN * 16];
__device__ float g_t1[S_LEN * 16];
__device__ float g_t2[S_LEN * 16];

// ================= shared helpers =================
__device__ __forceinline__ uint32_t smem_u32(const void* p) {
    return (uint32_t)__cvta_generic_to_shared(p);
}
__device__ __forceinline__ uint32_t pack2(__nv_bfloat16 a, __nv_bfloat16 b) {
    uint16_t ra = *(uint16_t*)&a, rb = *(uint16_t*)&b;
    return (uint32_t)ra | ((uint32_t)rb << 16);
}
__device__ __forceinline__ uint32_t pack2h(__half a, __half b) {
    uint16_t ra = *(uint16_t*)&a, rb = *(uint16_t*)&b;
    return (uint32_t)ra | ((uint32_t)rb << 16);
}
__device__ __forceinline__ void ldsm4(uint32_t* r, uint32_t addr) {
    asm volatile("ldmatrix.sync.aligned.m8n8.x4.shared.b16 {%0,%1,%2,%3}, [%4];"
                 : "=r"(r[0]), "=r"(r[1]), "=r"(r[2]), "=r"(r[3]) : "r"(addr));
}
__device__ __forceinline__ void mma_bf16(float* c, const uint32_t* a, const uint32_t* b) {
    asm volatile("mma.sync.aligned.m16n8k16.row.col.f32.bf16.bf16.f32 "
                 "{%0,%1,%2,%3}, {%4,%5,%6,%7}, {%8,%9}, {%0,%1,%2,%3};"
                 : "+f"(c[0]), "+f"(c[1]), "+f"(c[2]), "+f"(c[3])
                 : "r"(a[0]), "r"(a[1]), "r"(a[2]), "r"(a[3]), "r"(b[0]), "r"(b[1]));
}
__device__ __forceinline__ void mma_f16(float* c, const uint32_t* a, const uint32_t* b) {
    asm volatile("mma.sync.aligned.m16n8k16.row.col.f32.f16.f16.f32 "
                 "{%0,%1,%2,%3}, {%4,%5,%6,%7}, {%8,%9}, {%0,%1,%2,%3};"
                 : "+f"(c[0]), "+f"(c[1]), "+f"(c[2]), "+f"(c[3])
                 : "r"(a[0]), "r"(a[1]), "r"(a[2]), "r"(a[3]), "r"(b[0]), "r"(b[1]));
}
// fp32 -> fp16 hi + fp16 lo (A side: ~22-bit representation)
__device__ __forceinline__ void cvt8_f16_hilo(__half* hi_p, __half* lo_p, float4 v) {
    __half h0 = __float2half_rn(v.x), h1 = __float2half_rn(v.y);
    __half h2 = __float2half_rn(v.z), h3 = __float2half_rn(v.w);
    __half l0 = __float2half_rn(v.x - __half2float(h0));
    __half l1 = __float2half_rn(v.y - __half2float(h1));
    __half l2 = __float2half_rn(v.z - __half2float(h2));
    __half l3 = __float2half_rn(v.w - __half2float(h3));
    uint2 wh; wh.x = pack2h(h0, h1); wh.y = pack2h(h2, h3);
    uint2 wl; wl.x = pack2h(l0, l1); wl.y = pack2h(l2, l3);
    *(uint2*)hi_p = wh;
    *(uint2*)lo_p = wl;
}
// fp32 -> fp16 hi only (B / weight side)
__device__ __forceinline__ void cvt8_f16_hi(__half* hi_p, float4 v) {
    __half h0 = __float2half_rn(v.x), h1 = __float2half_rn(v.y);
    __half h2 = __float2half_rn(v.z), h3 = __float2half_rn(v.w);
    uint2 wh; wh.x = pack2h(h0, h1); wh.y = pack2h(h2, h3);
    *(uint2*)hi_p = wh;
}
__device__ __forceinline__ void cvt_store8(__nv_bfloat16* hi_p, __nv_bfloat16* lo_p, float4 v) {
    __nv_bfloat16 h0 = __float2bfloat16_rn(v.x);
    __nv_bfloat16 h1 = __float2bfloat16_rn(v.y);
    __nv_bfloat16 h2 = __float2bfloat16_rn(v.z);
    __nv_bfloat16 h3 = __float2bfloat16_rn(v.w);
    __nv_bfloat16 l0 = __float2bfloat16_rn(v.x - __bfloat162float(h0));
    __nv_bfloat16 l1 = __float2bfloat16_rn(v.y - __bfloat162float(h1));
    __nv_bfloat16 l2 = __float2bfloat16_rn(v.z - __bfloat162float(h2));
    __nv_bfloat16 l3 = __float2bfloat16_rn(v.w - __bfloat162float(h3));
    uint2 wh; wh.x = pack2(h0, h1); wh.y = pack2(h2, h3);
    uint2 wl; wl.x = pack2(l0, l1); wl.y = pack2(l2, l3);
    *(uint2*)hi_p = wh;
    *(uint2*)lo_p = wl;
}
__device__ __forceinline__ void split_pair(float a, float b, uint32_t* hi, uint32_t* lo) {
    __nv_bfloat16 ha = __float2bfloat16_rn(a), hb = __float2bfloat16_rn(b);
    __nv_bfloat16 la = __float2bfloat16_rn(a - __bfloat162float(ha));
    __nv_bfloat16 lb = __float2bfloat16_rn(b - __bfloat162float(hb));
    *hi = pack2(ha, hb);
    *lo = pack2(la, lb);
}

// ---------------- rmsnorm ----------------
__global__ void rmsnorm_kernel(const float* __restrict__ x, const float* __restrict__ w,
                               float* __restrict__ o, int D) {
    int row = blockIdx.x;
    const float* xr = x + (size_t)row * D;
    float* orow = o + (size_t)row * D;
    float ss = 0.f;
    for (int c = threadIdx.x; c < D; c += blockDim.x) {
        float v = xr[c];
        ss += v * v;
    }
    __shared__ float sred[32];
    for (int off = 16; off; off >>= 1) ss += __shfl_xor_sync(0xffffffffu, ss, off);
    if ((threadIdx.x & 31) == 0) sred[threadIdx.x >> 5] = ss;
    __syncthreads();
    if (threadIdx.x < 32) {
        float v = (threadIdx.x < (blockDim.x >> 5)) ? sred[threadIdx.x] : 0.f;
        for (int off = 16; off; off >>= 1) v += __shfl_xor_sync(0xffffffffu, v, off);
        if (threadIdx.x == 0) sred[0] = v;
    }
    __syncthreads();
    float inv = rsqrtf(sred[0] / (float)D + 1e-5f);
    for (int c = threadIdx.x; c < D; c += blockDim.x)
        orow[c] = xr[c] * inv * w[c];
}

// ---------------- LoRA down-projection: T[M,16] = X[M,K] @ A[16,K]^T (tiled) ----------------
__global__ void lora_a_kernel(const float* __restrict__ X, const float* __restrict__ A,
                              float* __restrict__ T, int K) {
    __shared__ float Xs[16][132];
    __shared__ float As[16][132];
    int m0 = blockIdx.x * 16;
    int tid = threadIdx.x;          // 256 threads
    int mi = tid >> 4, ni = tid & 15;
    float acc = 0.f;
    for (int k0 = 0; k0 < K; k0 += 128) {
#pragma unroll
        for (int i = 0; i < 2; i++) {
            int u = tid + i * 256;
            int r = u >> 5, c = (u & 31) * 4;
            *(float4*)&Xs[r][c] = *(const float4*)&X[(size_t)(m0 + r) * K + k0 + c];
            *(float4*)&As[r][c] = *(const float4*)&A[(size_t)r * K + k0 + c];
        }
        __syncthreads();
#pragma unroll
        for (int c = 0; c < 128; c += 4) {
            float4 x = *(float4*)&Xs[mi][c];
            float4 a = *(float4*)&As[ni][c];
            acc += x.x * a.x + x.y * a.y + x.z * a.z + x.w * a.w;
        }
        __syncthreads();
    }
    T[(m0 + mi) * 16 + ni] = acc;
}

// ================= fp16 2-term tensor-core GEMM =================
// C[M,N] = (Ahi+Alo)[M,K] @ fp16(B)[N,K]^T  (+ 2*T@LB^T)  (+ resid)
// BM=BN=128, BK=32, 256 threads (8 warps, 2x4), warp tile 64x32.
#define TS_A 40          // padded smem row stride in fp16 elems
#define STG_ELEMS (3 * 128 * TS_A)      // Ahi, Alo, Bhi
#define STG_BYTES (STG_ELEMS * 2)       // 30720
#define AHI_OFF 0
#define ALO_OFF (128 * TS_A)
#define BHI_OFF (2 * 128 * TS_A)
#define GEMM_SMEM_BYTES (2 * STG_BYTES + 2 * 128 * 16 * 4)   // 77824

__global__ void __launch_bounds__(256) sgemm_lora(
    const float* __restrict__ A, const float* __restrict__ B, float* __restrict__ C,
    int M, int N, int K,
    const float* __restrict__ T, const float* __restrict__ LB,
    const float* __restrict__ resid) {
    extern __shared__ char smem_raw[];
    __half* sH = (__half*)smem_raw;
    float* Ts = (float*)(smem_raw + 2 * STG_BYTES);
    float* LBs = Ts + 128 * 16;

    int tid = threadIdx.x;
    int lane = tid & 31, warp = tid >> 5;
    int m0 = blockIdx.y * 128;
    int n0 = blockIdx.x * 128;

    if (T != nullptr) {
        for (int i = tid; i < 128 * 4; i += 256) {
            int r = i >> 2, c = (i & 3) * 4;
            *(float4*)&Ts[r * 16 + c]  = *(const float4*)&T[(size_t)(m0 + r) * 16 + c];
            *(float4*)&LBs[r * 16 + c] = *(const float4*)&LB[(size_t)(n0 + r) * 16 + c];
        }
    }

    int glr = tid >> 3;            // 0..31 row group
    int glk = (tid & 7) * 4;       // float4 k offset

    int wm = (warp >> 2) * 64;
    int wn = (warp & 3) * 32;
    int a_row = wm + (lane & 15);
    int a_kof = (lane >> 4) << 3;
    int b_row = wn + (lane & 7) + ((lane >> 4) << 3);
    int b_kof = ((lane >> 3) & 1) << 3;

    uint32_t sbase = smem_u32(smem_raw);

    float acc[4][4][4];
#pragma unroll
    for (int i = 0; i < 4; i++)
#pragma unroll
        for (int j = 0; j < 4; j++)
#pragma unroll
            for (int e = 0; e < 4; e++) acc[i][j][e] = 0.f;

    float4 av[4], bv[4];
#pragma unroll
    for (int i = 0; i < 4; i++) {
        av[i] = *(const float4*)&A[(size_t)(m0 + glr + 32 * i) * K + glk];
        bv[i] = *(const float4*)&B[(size_t)(n0 + glr + 32 * i) * K + glk];
    }
    {
        __half* sa = sH;  // stage 0
#pragma unroll
        for (int i = 0; i < 4; i++) {
            int off = (glr + 32 * i) * TS_A + glk;
            cvt8_f16_hilo(sa + AHI_OFF + off, sa + ALO_OFF + off, av[i]);
            cvt8_f16_hi(sa + BHI_OFF + off, bv[i]);
        }
    }
    __syncthreads();

    int s = 0;
    for (int k0 = 0; k0 < K; k0 += 32) {
        bool more = (k0 + 32 < K);
        if (more) {
#pragma unroll
            for (int i = 0; i < 4; i++) {
                av[i] = *(const float4*)&A[(size_t)(m0 + glr + 32 * i) * K + k0 + 32 + glk];
                bv[i] = *(const float4*)&B[(size_t)(n0 + glr + 32 * i) * K + k0 + 32 + glk];
            }
        }
        uint32_t sgbase = sbase + (uint32_t)s * STG_BYTES;
#pragma unroll
        for (int kk = 0; kk < 32; kk += 16) {
            uint32_t ahi[4][4], alo[4][4], bhi[2][4];
#pragma unroll
            for (int mi = 0; mi < 4; mi++) {
                uint32_t off = ((uint32_t)(a_row + 16 * mi) * TS_A + kk + a_kof) * 2;
                ldsm4(ahi[mi], sgbase + AHI_OFF * 2 + off);
                ldsm4(alo[mi], sgbase + ALO_OFF * 2 + off);
            }
#pragma unroll
            for (int j = 0; j < 2; j++) {
                uint32_t off = ((uint32_t)(b_row + 16 * j) * TS_A + kk + b_kof) * 2;
                ldsm4(bhi[j], sgbase + BHI_OFF * 2 + off);
            }
#pragma unroll
            for (int mi = 0; mi < 4; mi++)
#pragma unroll
                for (int nt = 0; nt < 4; nt++)
                    mma_f16(acc[mi][nt], ahi[mi], &bhi[nt >> 1][(nt & 1) * 2]);
#pragma unroll
            for (int mi = 0; mi < 4; mi++)
#pragma unroll
                for (int nt = 0; nt < 4; nt++)
                    mma_f16(acc[mi][nt], alo[mi], &bhi[nt >> 1][(nt & 1) * 2]);
        }
        if (more) {
            __half* sa = sH + (s ^ 1) * STG_ELEMS;
#pragma unroll
            for (int i = 0; i < 4; i++) {
                int off = (glr + 32 * i) * TS_A + glk;
                cvt8_f16_hilo(sa + AHI_OFF + off, sa + ALO_OFF + off, av[i]);
                cvt8_f16_hi(sa + BHI_OFF + off, bv[i]);
            }
        }
        __syncthreads();
        s ^= 1;
    }

    // ---- LoRA rank-16 epilogue ----
    int rg = lane >> 2;
    int cg = (lane & 3) * 2;
    if (T != nullptr) {
#pragma unroll
        for (int r = 0; r < 16; r++) {
            float tm[8], tn[8];
#pragma unroll
            for (int mi = 0; mi < 4; mi++) {
                tm[mi * 2 + 0] = 2.0f * Ts[(wm + mi * 16 + rg) * 16 + r];
                tm[mi * 2 + 1] = 2.0f * Ts[(wm + mi * 16 + rg + 8) * 16 + r];
            }
#pragma unroll
            for (int nt = 0; nt < 4; nt++) {
                tn[nt * 2 + 0] = LBs[(wn + nt * 8 + cg) * 16 + r];
                tn[nt * 2 + 1] = LBs[(wn + nt * 8 + cg + 1) * 16 + r];
            }
#pragma unroll
            for (int mi = 0; mi < 4; mi++)
#pragma unroll
                for (int nt = 0; nt < 4; nt++) {
                    acc[mi][nt][0] += tm[mi * 2 + 0] * tn[nt * 2 + 0];
                    acc[mi][nt][1] += tm[mi * 2 + 0] * tn[nt * 2 + 1];
                    acc[mi][nt][2] += tm[mi * 2 + 1] * tn[nt * 2 + 0];
                    acc[mi][nt][3] += tm[mi * 2 + 1] * tn[nt * 2 + 1];
                }
        }
    }

#pragma unroll
    for (int mi = 0; mi < 4; mi++) {
#pragma unroll
        for (int p = 0; p < 2; p++) {
            size_t row = (size_t)(m0 + wm + mi * 16 + rg + 8 * p);
#pragma unroll
            for (int nt = 0; nt < 4; nt++) {
                size_t col = n0 + wn + nt * 8 + cg;
                float2 o;
                o.x = acc[mi][nt][p * 2 + 0];
                o.y = acc[mi][nt][p * 2 + 1];
                if (resid != nullptr) {
                    float2 rr = *(const float2*)&resid[row * N + col];
                    o.x += rr.x; o.y += rr.y;
                }
                *(float2*)&C[row * N + col] = o;
            }
        }
    }
}

// ---------------- RoPE ----------------
__global__ void rope_kernel(float* __restrict__ x, const float* __restrict__ cosb,
                            const float* __restrict__ sinb, int H) {
    int idx = blockIdx.x * blockDim.x + threadIdx.x;
    int total = S_LEN * H * 64;
    if (idx >= total) return;
    int i = idx & 63;
    int sh = idx >> 6;
    int s = sh / H;
    float c = cosb[s * 64 + i];
    float sn = sinb[s * 64 + i];
    float* p = x + (size_t)sh * 128 + 2 * i;
    float a = p[0], b = p[1];
    p[0] = a * c - b * sn;
    p[1] = a * sn + b * c;
}

// ================= tensor-core causal flash attention (bf16 3-term) =================
#define FQH 0
#define FQL 16384
#define FKH 32768
#define FKL 49152
#define FVH 65536
#define FVL 81920
#define FPH 98304
#define FPL 106496
#define FSTAT 114688
#define FLASH_TC_SMEM (114688 + 1024)

__global__ void __launch_bounds__(256) flash_tc(
    const float* __restrict__ Q, const float* __restrict__ K, const float* __restrict__ V,
    float* __restrict__ O) {
    extern __shared__ char smc[];
    uint32_t sb = smem_u32(smc);
    float* maxp = (float*)(smc + FSTAT);
    float* sump = maxp + 128;

    int h = blockIdx.x;
    int qb = (gridDim.y - 1) - blockIdx.y;
    int kvh = h >> 2;
    int tid = threadIdx.x;
    int lane = tid & 31, wid = tid >> 5;
    int warp_m = wid & 3, warp_n = wid >> 2;
    int q0 = qb * 64;

    int rg = lane >> 2;
    int cg = (lane & 3) * 2;
    int a_row16 = (lane & 15);
    int a_sel = lane >> 4;
    int b_roff = (lane & 7) + ((lane >> 4) << 3);
    int b_sel = (lane >> 3) & 1;

#pragma unroll
    for (int i = 0; i < 8; i++) {
        int u = tid + i * 256;
        int r = u >> 5;
        int col = (u & 31) * 4;
        float4 v = *(const float4*)&Q[(size_t)(q0 + r) * D_MODEL + h * HEAD_DIM + col];
        uint32_t adr = sb + FQH + r * 256 + ((((col >> 3) ^ (r & 7))) << 4) + (col & 7) * 2;
        __nv_bfloat16 tmp_h[4], tmp_l[4];
        cvt_store8(tmp_h, tmp_l, v);
        uint2 wh = *(uint2*)tmp_h, wl = *(uint2*)tmp_l;
        asm volatile("st.shared.v2.b32 [%0], {%1,%2};" :: "r"(adr), "r"(wh.x), "r"(wh.y) : "memory");
        asm volatile("st.shared.v2.b32 [%0], {%1,%2};" :: "r"(adr + (FQL - FQH)), "r"(wl.x), "r"(wl.y) : "memory");
    }

    float m_prev0 = -1e30f, m_prev1 = -1e30f, l0 = 0.f, l1 = 0.f;
    float oacc[8][4];
#pragma unroll
    for (int t = 0; t < 8; t++)
#pragma unroll
        for (int e = 0; e < 4; e++) oacc[t][e] = 0.f;

    int row_g0 = q0 + 16 * warp_m + rg;
    int row_g1 = row_g0 + 8;

    for (int kb = 0; kb <= qb; kb++) {
        int k0 = kb * 64;
        __syncthreads();
#pragma unroll
        for (int i = 0; i < 8; i++) {
            int u = tid + i * 256;
            int r = u >> 5;
            int col = (u & 31) * 4;
            float4 v = *(const float4*)&K[(size_t)(k0 + r) * KVDIM + kvh * HEAD_DIM + col];
            uint32_t adr = sb + FKH + r * 256 + ((((col >> 3) ^ (r & 7))) << 4) + (col & 7) * 2;
            __nv_bfloat16 th[4], tl[4];
            cvt_store8(th, tl, v);
            uint2 wh = *(uint2*)th, wl = *(uint2*)tl;
            asm volatile("st.shared.v2.b32 [%0], {%1,%2};" :: "r"(adr), "r"(wh.x), "r"(wh.y) : "memory");
            asm volatile("st.shared.v2.b32 [%0], {%1,%2};" :: "r"(adr + (FKL - FKH)), "r"(wl.x), "r"(wl.y) : "memory");
        }
#pragma unroll
        for (int i = 0; i < 4; i++) {
            int u = tid + i * 256;
            int kp = u & 31;
            int d = (u >> 5) * 4;
            float4 va = *(const float4*)&V[(size_t)(k0 + 2 * kp) * KVDIM + kvh * HEAD_DIM + d];
            float4 vb = *(const float4*)&V[(size_t)(k0 + 2 * kp + 1) * KVDIM + kvh * HEAD_DIM + d];
            const float* pa = (const float*)&va;
            const float* pb = (const float*)&vb;
            int colk = 2 * kp;
#pragma unroll
            for (int j = 0; j < 4; j++) {
                int dr = d + j;
                uint32_t hi, lo;
                split_pair(pa[j], pb[j], &hi, &lo);
                uint32_t adr = sb + FVH + dr * 128 + ((((colk >> 3) ^ (dr & 7))) << 4) + (colk & 7) * 2;
                asm volatile("st.shared.b32 [%0], %1;" :: "r"(adr), "r"(hi) : "memory");
                asm volatile("st.shared.b32 [%0], %1;" :: "r"(adr + (FVL - FVH)), "r"(lo) : "memory");
            }
        }
        __syncthreads();

        float sacc[4][4];
#pragma unroll
        for (int nt = 0; nt < 4; nt++)
#pragma unroll
            for (int e = 0; e < 4; e++) sacc[nt][e] = 0.f;
        int aq_row = 16 * warp_m + a_row16;
#pragma unroll
        for (int ks = 0; ks < 8; ks++) {
            uint32_t ahi[4], alo[4], khi[2][4], klo[2][4];
            uint32_t qa = sb + FQH + aq_row * 256 + ((((2 * ks + a_sel) ^ (aq_row & 7))) << 4);
            ldsm4(ahi, qa);
            ldsm4(alo, qa + (FQL - FQH));
#pragma unroll
            for (int j = 0; j < 2; j++) {
                int krow = 32 * warp_n + 16 * j + b_roff;
                uint32_t ka = sb + FKH + krow * 256 + ((((2 * ks + b_sel) ^ (krow & 7))) << 4);
                ldsm4(khi[j], ka);
                ldsm4(klo[j], ka + (FKL - FKH));
            }
#pragma unroll
            for (int nt = 0; nt < 4; nt++) {
                mma_bf16(sacc[nt], ahi, &khi[nt >> 1][(nt & 1) * 2]);
                mma_bf16(sacc[nt], ahi, &klo[nt >> 1][(nt & 1) * 2]);
                mma_bf16(sacc[nt], alo, &khi[nt >> 1][(nt & 1) * 2]);
            }
        }
        const float scale = 0.08838834764831845f;
#pragma unroll
        for (int nt = 0; nt < 4; nt++) {
            int cb = k0 + 32 * warp_n + 8 * nt + cg;
#pragma unroll
            for (int e = 0; e < 4; e++) sacc[nt][e] *= scale;
            if (kb == qb) {
                if (cb > row_g0) sacc[nt][0] = -1e30f;
                if (cb + 1 > row_g0) sacc[nt][1] = -1e30f;
                if (cb > row_g1) sacc[nt][2] = -1e30f;
                if (cb + 1 > row_g1) sacc[nt][3] = -1e30f;
            }
        }

        float mx0 = -1e30f, mx1 = -1e30f;
#pragma unroll
        for (int nt = 0; nt < 4; nt++) {
            mx0 = fmaxf(mx0, fmaxf(sacc[nt][0], sacc[nt][1]));
            mx1 = fmaxf(mx1, fmaxf(sacc[nt][2], sacc[nt][3]));
        }
        mx0 = fmaxf(mx0, __shfl_xor_sync(0xffffffffu, mx0, 1));
        mx0 = fmaxf(mx0, __shfl_xor_sync(0xffffffffu, mx0, 2));
        mx1 = fmaxf(mx1, __shfl_xor_sync(0xffffffffu, mx1, 1));
        mx1 = fmaxf(mx1, __shfl_xor_sync(0xffffffffu, mx1, 2));
        if ((lane & 3) == 0) {
            maxp[warp_n * 64 + 16 * warp_m + rg] = mx0;
            maxp[warp_n * 64 + 16 * warp_m + rg + 8] = mx1;
        }
        __syncthreads();
        int sidx0 = 16 * warp_m + rg, sidx1 = sidx0 + 8;
        float mb0 = fmaxf(maxp[sidx0], maxp[64 + sidx0]);
        float mb1 = fmaxf(maxp[sidx1], maxp[64 + sidx1]);
        float mn0 = fmaxf(m_prev0, mb0), mn1 = fmaxf(m_prev1, mb1);
        float corr0 = __expf(m_prev0 - mn0), corr1 = __expf(m_prev1 - mn1);

        float ps0 = 0.f, ps1 = 0.f;
#pragma unroll
        for (int nt = 0; nt < 4; nt++) {
            float p00 = __expf(sacc[nt][0] - mn0);
            float p01 = __expf(sacc[nt][1] - mn0);
            float p10 = __expf(sacc[nt][2] - mn1);
            float p11 = __expf(sacc[nt][3] - mn1);
            ps0 += p00 + p01;
            ps1 += p10 + p11;
            int col = 32 * warp_n + 8 * nt + cg;
            int r0 = 16 * warp_m + rg, r1 = r0 + 8;
            uint32_t hi, lo;
            split_pair(p00, p01, &hi, &lo);
            uint32_t a0 = sb + FPH + r0 * 128 + ((((col >> 3) ^ (r0 & 7))) << 4) + (col & 7) * 2;
            asm volatile("st.shared.b32 [%0], %1;" :: "r"(a0), "r"(hi) : "memory");
            asm volatile("st.shared.b32 [%0], %1;" :: "r"(a0 + (FPL - FPH)), "r"(lo) : "memory");
            split_pair(p10, p11, &hi, &lo);
            uint32_t a1 = sb + FPH + r1 * 128 + ((((col >> 3) ^ (r1 & 7))) << 4) + (col & 7) * 2;
            asm volatile("st.shared.b32 [%0], %1;" :: "r"(a1), "r"(hi) : "memory");
            asm volatile("st.shared.b32 [%0], %1;" :: "r"(a1 + (FPL - FPH)), "r"(lo) : "memory");
        }
        ps0 += __shfl_xor_sync(0xffffffffu, ps0, 1);
        ps0 += __shfl_xor_sync(0xffffffffu, ps0, 2);
        ps1 += __shfl_xor_sync(0xffffffffu, ps1, 1);
        ps1 += __shfl_xor_sync(0xffffffffu, ps1, 2);
        if ((lane & 3) == 0) {
            sump[warp_n * 64 + sidx0] = ps0;
            sump[warp_n * 64 + sidx1] = ps1;
        }
#pragma unroll
        for (int t = 0; t < 8; t++) {
            oacc[t][0] *= corr0; oacc[t][1] *= corr0;
            oacc[t][2] *= corr1; oacc[t][3] *= corr1;
        }
        l0 *= corr0; l1 *= corr1;
        m_prev0 = mn0; m_prev1 = mn1;
        __syncthreads();
        l0 += sump[sidx0] + sump[64 + sidx0];
        l1 += sump[sidx1] + sump[64 + sidx1];

#pragma unroll
        for (int kp = 0; kp < 4; kp++) {
            uint32_t phi[4], plo[4], vhi[4][4], vlo[4][4];
            int prow = 16 * warp_m + a_row16;
            uint32_t pa = sb + FPH + prow * 128 + ((((2 * kp + a_sel) ^ (prow & 7))) << 4);
            ldsm4(phi, pa);
            ldsm4(plo, pa + (FPL - FPH));
#pragma unroll
            for (int j = 0; j < 4; j++) {
                int vrow = 64 * warp_n + 16 * j + b_roff;
                uint32_t va = sb + FVH + vrow * 128 + ((((2 * kp + b_sel) ^ (vrow & 7))) << 4);
                ldsm4(vhi[j], va);
                ldsm4(vlo[j], va + (FVL - FVH));
            }
#pragma unroll
            for (int t = 0; t < 8; t++) {
                mma_bf16(oacc[t], phi, &vhi[t >> 1][(t & 1) * 2]);
                mma_bf16(oacc[t], phi, &vlo[t >> 1][(t & 1) * 2]);
                mma_bf16(oacc[t], plo, &vhi[t >> 1][(t & 1) * 2]);
            }
        }
    }

    float inv0 = 1.f / l0, inv1 = 1.f / l1;
#pragma unroll
    for (int t = 0; t < 8; t++) {
        int col = h * HEAD_DIM + 64 * warp_n + 8 * t + cg;
        float2 o0 = make_float2(oacc[t][0] * inv0, oacc[t][1] * inv0);
        float2 o1 = make_float2(oacc[t][2] * inv1, oacc[t][3] * inv1);
        *(float2*)&O[(size_t)row_g0 * D_MODEL + col] = o0;
        *(float2*)&O[(size_t)row_g1 * D_MODEL + col] = o1;
    }
}

// ---------------- silu(gate) * up ----------------
__global__ void silu_mul_kernel(const float* __restrict__ g, const float* __restrict__ u,
                                float* __restrict__ o, int n) {
    int i = blockIdx.x * blockDim.x + threadIdx.x;
    if (i < n) {
        float x = g[i];
        float s = x / (1.f + __expf(-x));
        o[i] = s * u[i];
    }
}

// ---------------- launch ----------------
extern "C" void kernel_launch(void* const* d_in, const int* in_sizes, int n_in,
                              void* d_out, int out_size) {
    const float* data = (const float*)d_in[0];
    const float* cosb = (const float*)d_in[2];
    const float* sinb = (const float*)d_in[3];
    const float* attn_norm_w = (const float*)d_in[4];
    const float* wq = (const float*)d_in[5];
    const float* wk = (const float*)d_in[6];
    const float* wv = (const float*)d_in[7];
    const float* wo = (const float*)d_in[8];
    const float* wq_a = (const float*)d_in[9];
    const float* wq_b = (const float*)d_in[10];
    const float* wk_a = (const float*)d_in[11];
    const float* wk_b = (const float*)d_in[12];
    const float* wv_a = (const float*)d_in[13];
    const float* wv_b = (const float*)d_in[14];
    const float* wo_a = (const float*)d_in[15];
    const float* wo_b = (const float*)d_in[16];
    const float* ffn_norm_w = (const float*)d_in[17];
    const float* w1 = (const float*)d_in[18];
    const float* w2 = (const float*)d_in[19];
    const float* w3 = (const float*)d_in[20];
    const float* w1_a = (const float*)d_in[21];
    const float* w1_b = (const float*)d_in[22];
    const float* w2_a = (const float*)d_in[23];
    const float* w2_b = (const float*)d_in[24];
    const float* w3_a = (const float*)d_in[25];
    const float* w3_b = (const float*)d_in[26];
    float* out = (float*)d_out;

    float *h, *q, *k, *v, *attn, *res1, *f, *gate, *up, *t0, *t1, *t2;
    cudaGetSymbolAddress((void**)&h, g_h);
    cudaGetSymbolAddress((void**)&q, g_q);
    cudaGetSymbolAddress((void**)&k, g_k);
    cudaGetSymbolAddress((void**)&v, g_v);
    cudaGetSymbolAddress((void**)&attn, g_attn);
    cudaGetSymbolAddress((void**)&res1, g_res1);
    cudaGetSymbolAddress((void**)&f, g_f);
    cudaGetSymbolAddress((void**)&gate, g_gate);
    cudaGetSymbolAddress((void**)&up, g_up);
    cudaGetSymbolAddress((void**)&t0, g_t0);
    cudaGetSymbolAddress((void**)&t1, g_t1);
    cudaGetSymbolAddress((void**)&t2, g_t2);

    cudaFuncSetAttribute(sgemm_lora, cudaFuncAttributeMaxDynamicSharedMemorySize,
                         GEMM_SMEM_BYTES);
    cudaFuncSetAttribute(flash_tc, cudaFuncAttributeMaxDynamicSharedMemorySize,
                         FLASH_TC_SMEM);

    // 1) attn rmsnorm
    rmsnorm_kernel<<<S_LEN, 256>>>(data, attn_norm_w, h, D_MODEL);

    // 2) q/k/v projections with fused LoRA
    lora_a_kernel<<<S_LEN / 16, 256>>>(h, wq_a, t0, D_MODEL);
    lora_a_kernel<<<S_LEN / 16, 256>>>(h, wk_a, t1, D_MODEL);
    lora_a_kernel<<<S_LEN / 16, 256>>>(h, wv_a, t2, D_MODEL);
    sgemm_lora<<<dim3(D_MODEL / 128, S_LEN / 128), 256, GEMM_SMEM_BYTES>>>(h, wq, q, S_LEN, D_MODEL, D_MODEL, t0, wq_b, nullptr);
    sgemm_lora<<<dim3(KVDIM / 128, S_LEN / 128), 256, GEMM_SMEM_BYTES>>>(h, wk, k, S_LEN, KVDIM, D_MODEL, t1, wk_b, nullptr);
    sgemm_lora<<<dim3(KVDIM / 128, S_LEN / 128), 256, GEMM_SMEM_BYTES>>>(h, wv, v, S_LEN, KVDIM, D_MODEL, t2, wv_b, nullptr);

    // 3) RoPE
    rope_kernel<<<(S_LEN * N_HEADS * 64) / 256, 256>>>(q, cosb, sinb, N_HEADS);
    rope_kernel<<<(S_LEN * N_KV_HEADS * 64) / 256, 256>>>(k, cosb, sinb, N_KV_HEADS);

    // 4) attention (tensor-core flash)
    flash_tc<<<dim3(N_HEADS, S_LEN / 64), 256, FLASH_TC_SMEM>>>(q, k, v, attn);

    // 5) output projection + residual
    lora_a_kernel<<<S_LEN / 16, 256>>>(attn, wo_a, t0, D_MODEL);
    sgemm_lora<<<dim3(D_MODEL / 128, S_LEN / 128), 256, GEMM_SMEM_BYTES>>>(attn, wo, res1, S_LEN, D_MODEL, D_MODEL, t0, wo_b, data);

    // 6) ffn rmsnorm
    rmsnorm_kernel<<<S_LEN, 256>>>(res1, ffn_norm_w, f, D_MODEL);

    // 7) gate / up
    lora_a_kernel<<<S_LEN / 16, 256>>>(f, w1_a, t0, D_MODEL);
    lora_a_kernel<<<S_LEN / 16, 256>>>(f, w3_a, t1, D_MODEL);
    sgemm_lora<<<dim3(FF_DIM / 128, S_LEN / 128), 256, GEMM_SMEM_BYTES>>>(f, w1, gate, S_LEN, FF_DIM, D_MODEL, t0, w1_b, nullptr);
    sgemm_lora<<<dim3(FF_DIM / 128, S_LEN / 128), 256, GEMM_SMEM_BYTES>>>(f, w3, up, S_LEN, FF_DIM, D_MODEL, t1, w3_b, nullptr);

    // 8) silu * up
    silu_mul_kernel<<<(S_LEN * FF_DIM) / 256, 256>>>(gate, up, gate, S_LEN * FF_DIM);

    // 9) down projection + residual -> out
    lora_a_kernel<<<S_LEN / 16, 256>>>(gate, w2_a, t0, FF_DIM);
    sgemm_lora<<<dim3(D_MODEL / 128, S_LEN / 128), 256, GEMM_SMEM_BYTES>>>(gate, w2, out, S_LEN, D_MODEL, FF_DIM, t0, w2_b, res1);
}